// round 16
// baseline (speedup 1.0000x reference)
#include <cuda_runtime.h>
#include <cuda_bf16.h>
#include <cuda_fp16.h>
#include <math.h>
#include <stdint.h>

// ---------------------------------------------------------------------------
// Problem constants
// ---------------------------------------------------------------------------
#define BB    2
#define SSEQ  1024
#define DDIM  1024
#define HHH   16
#define DKV   64
#define DHH   4096
#define LLAY  8
#define VVOC  256
#define MM    (BB*SSEQ)        // 2048
#define NQKV  3072

// ---------------------------------------------------------------------------
// Scratch (device globals: allocation-free)
// ---------------------------------------------------------------------------
__device__ float g_x   [MM*DDIM];
__device__ float g_o   [MM*DDIM];
__device__ float g_h   [MM*DDIM];
__device__ float g_t   [MM*DHH];
__device__ __nv_bfloat16 g_qkvhi[MM*NQKV], g_qkvlo[MM*NQKV];

// pre-split fp16 weight planes (transposed [N,K])
__device__ __half g_Wqkv_hi[LLAY*NQKV*DDIM], g_Wqkv_lo[LLAY*NQKV*DDIM];
__device__ __half g_Wo_hi  [LLAY*DDIM*DDIM], g_Wo_lo  [LLAY*DDIM*DDIM];
__device__ __half g_W1_hi  [LLAY*DHH*DDIM],  g_W1_lo  [LLAY*DHH*DDIM];
__device__ __half g_W2_hi  [LLAY*DDIM*DHH],  g_W2_lo  [LLAY*DDIM*DHH];
__device__ __half g_Wr_hi  [VVOC*DDIM],      g_Wr_lo  [VVOC*DDIM];
__device__ float  g_bqkv[LLAY*NQKV];

// ---------------------------------------------------------------------------
// Helpers
// ---------------------------------------------------------------------------
__device__ __forceinline__ uint32_t smem_u32(const void* p) {
    uint32_t a;
    asm("{ .reg .u64 t; cvta.to.shared.u64 t, %1; cvt.u32.u64 %0, t; }"
        : "=r"(a) : "l"(p));
    return a;
}

__device__ __forceinline__ void ldmx4(uint32_t* r, uint32_t addr) {
    asm volatile("ldmatrix.sync.aligned.m8n8.x4.shared.b16 {%0,%1,%2,%3}, [%4];"
        : "=r"(r[0]), "=r"(r[1]), "=r"(r[2]), "=r"(r[3]) : "r"(addr));
}

__device__ __forceinline__ void ldmx4t(uint32_t* r, uint32_t addr) {
    asm volatile("ldmatrix.sync.aligned.m8n8.x4.trans.shared.b16 {%0,%1,%2,%3}, [%4];"
        : "=r"(r[0]), "=r"(r[1]), "=r"(r[2]), "=r"(r[3]) : "r"(addr));
}

// bf16 inputs, f32 acc (attention)
__device__ __forceinline__ void mma16816(float* d, const uint32_t* a,
                                         uint32_t b0, uint32_t b1) {
    asm volatile("mma.sync.aligned.m16n8k16.row.col.f32.bf16.bf16.f32 "
        "{%0,%1,%2,%3}, {%4,%5,%6,%7}, {%8,%9}, {%0,%1,%2,%3};"
        : "+f"(d[0]), "+f"(d[1]), "+f"(d[2]), "+f"(d[3])
        : "r"(a[0]), "r"(a[1]), "r"(a[2]), "r"(a[3]), "r"(b0), "r"(b1));
}

// f16 inputs, f32 acc (GEMM main pass)
__device__ __forceinline__ void mma16816_h32(float* d, const uint32_t* a,
                                             uint32_t b0, uint32_t b1) {
    asm volatile("mma.sync.aligned.m16n8k16.row.col.f32.f16.f16.f32 "
        "{%0,%1,%2,%3}, {%4,%5,%6,%7}, {%8,%9}, {%0,%1,%2,%3};"
        : "+f"(d[0]), "+f"(d[1]), "+f"(d[2]), "+f"(d[3])
        : "r"(a[0]), "r"(a[1]), "r"(a[2]), "r"(a[3]), "r"(b0), "r"(b1));
}

// f16 inputs, f16 acc (GEMM correction pass)
__device__ __forceinline__ void mma16816_h16(uint32_t* d, const uint32_t* a,
                                             uint32_t b0, uint32_t b1) {
    asm volatile("mma.sync.aligned.m16n8k16.row.col.f16.f16.f16.f16 "
        "{%0,%1}, {%2,%3,%4,%5}, {%6,%7}, {%0,%1};"
        : "+r"(d[0]), "+r"(d[1])
        : "r"(a[0]), "r"(a[1]), "r"(a[2]), "r"(a[3]), "r"(b0), "r"(b1));
}

__device__ __forceinline__ void cp16(uint32_t dst, const void* src) {
    asm volatile("cp.async.cg.shared.global [%0], [%1], 16;"
        :: "r"(dst), "l"(src) : "memory");
}
#define CP_COMMIT() asm volatile("cp.async.commit_group;" ::: "memory")
#define CP_WAIT0()  asm volatile("cp.async.wait_group 0;" ::: "memory")

__device__ __forceinline__ float gelu_exact(float v) {
    return 0.5f * v * (1.0f + erff(v * 0.70710678118654752f));
}

#define LO_SCALE 4096.0f
#define LO_INV   (1.0f/4096.0f)

// fp16 hi-only pack (A staging)
__device__ __forceinline__ uint2 pack_f4h(float4 v) {
    __half2 p0 = __halves2half2(__float2half_rn(v.x), __float2half_rn(v.y));
    __half2 p1 = __halves2half2(__float2half_rn(v.z), __float2half_rn(v.w));
    uint2 r;
    r.x = *(uint32_t*)&p0;
    r.y = *(uint32_t*)&p1;
    return r;
}

__device__ __forceinline__ void split1(float v, __nv_bfloat16& hi, __nv_bfloat16& lo) {
    hi = __float2bfloat16(v);
    lo = __float2bfloat16(v - __bfloat162float(hi));
}

__device__ __forceinline__ void split1h(float v, __half& hi, __half& lo) {
    hi = __float2half_rn(v);
    lo = __float2half_rn((v - __half2float(hi)) * LO_SCALE);
}

// ---------------------------------------------------------------------------
// GEMM: C = act(A @ Bt^T + bias) + res
// A fp32 (packed to fp16 in staging); B pre-split fp16 hi/lo planes [N,K],
// staged via cp.async (no register round-trip, no split ALU).
// 2-pass: D = Ahi*Bhi (f32 acc) + Ahi*Blo' (f16 acc, Blo pre-scaled 2^12).
// BM in {128, 64}; BN = 128; BK = 32; 8 warps; double-buffered smem.
// ---------------------------------------------------------------------------
#define LDB 80

template<int BM, int MINB>
__global__ void __launch_bounds__(256, MINB)
gemm_mma(const float* __restrict__ A,
         const __half* __restrict__ Bhi, const __half* __restrict__ Blo,
         const float* __restrict__ bias, const float* __restrict__ res,
         float* __restrict__ Cf,
         __nv_bfloat16* __restrict__ Chi, __nv_bfloat16* __restrict__ Clo,
         int M, int N, int K, int gelu)
{
    constexpr int MT      = BM / 32;
    constexpr int AP      = BM / 32;
    constexpr int OFF_BHI = BM * LDB;
    constexpr int OFF_BLO = (BM + 128) * LDB;
    constexpr int STAGE   = (BM + 256) * LDB;

    extern __shared__ char sm[];
    const uint32_t smb = smem_u32(sm);

    const int tid  = threadIdx.x;
    const int lane = tid & 31;
    const int wid  = tid >> 5;
    const int wr   = wid >> 2;
    const int wc   = wid & 3;
    const int m0   = blockIdx.y * BM;
    const int n0   = blockIdx.x * 128;

    // A staging: 8 threads per 64B row (uint2 each)
    const int sc4  = tid & 7;
    const int srow = tid >> 3;
    const float* aP = A + (size_t)(m0 + srow) * K + sc4 * 4;

    // B staging via cp.async: 4 threads per 64B row (16B each)
    const int bch = tid & 3;
    const int brw = tid >> 2;          // 0..63
    const __half* bHP = Bhi + (size_t)(n0 + brw) * K + bch * 8;
    const __half* bLP = Blo + (size_t)(n0 + brw) * K + bch * 8;

    auto issueB = [&](int it) {
        const uint32_t sp = smb + (uint32_t)((it & 1) * STAGE) + OFF_BHI
                          + (uint32_t)(brw * LDB + bch * 16);
        const int koff = it * 32;
#pragma unroll
        for (int p = 0; p < 2; p++)
            cp16(sp + p * 64 * LDB, bHP + (size_t)p * 64 * K + koff);
#pragma unroll
        for (int p = 0; p < 2; p++)
            cp16(sp + (128 + p * 64) * LDB, bLP + (size_t)p * 64 * K + koff);
        CP_COMMIT();
    };

    float acc[MT][4][4];
    uint32_t corr[MT][4][2];
#pragma unroll
    for (int i = 0; i < MT; i++)
#pragma unroll
        for (int j = 0; j < 4; j++) {
#pragma unroll
            for (int q = 0; q < 4; q++) acc[i][j][q] = 0.0f;
            corr[i][j][0] = 0u; corr[i][j][1] = 0u;
        }

    float4 ra[AP];
    // ---- prologue: stage 0 ----
#pragma unroll
    for (int p = 0; p < AP; p++)
        ra[p] = __ldg((const float4*)(aP + (size_t)p * 32 * K));
    issueB(0);
    {
        char* sp = sm;
#pragma unroll
        for (int p = 0; p < AP; p++) {
            uint32_t off = (uint32_t)((srow + p * 32) * LDB + sc4 * 8);
            *(uint2*)(sp + off) = pack_f4h(ra[p]);
        }
    }
    CP_WAIT0();
    __syncthreads();

    const int nIt = K >> 5;
    for (int it = 0; it < nIt; ++it) {
        const int cur = it & 1;

        if (it + 1 < nIt) {
#pragma unroll
            for (int p = 0; p < AP; p++)
                ra[p] = __ldg((const float4*)(aP + (it + 1) * 32 + (size_t)p * 32 * K));
            issueB(it + 1);
        }

        const uint32_t stage = smb + cur * STAGE;
        const uint32_t aHiB = stage
            + (uint32_t)((wr * (BM/2) + (lane & 15)) * LDB + (lane >> 4) * 16);
        const uint32_t bHiB = stage + OFF_BHI + (uint32_t)((wc * 32 + lane) * LDB);

#pragma unroll
        for (int kc = 0; kc < 2; kc++) {
            uint32_t ahi[MT][4];
            uint32_t bh0[4], bh1[4], bl0[4], bl1[4];
#pragma unroll
            for (int mt = 0; mt < MT; mt++)
                ldmx4(ahi[mt], aHiB + mt * 16 * LDB + kc * 32);
            ldmx4(bh0, bHiB + kc * 32);
            ldmx4(bh1, bHiB + kc * 32 + 16);
            ldmx4(bl0, bHiB + (OFF_BLO - OFF_BHI) + kc * 32);
            ldmx4(bl1, bHiB + (OFF_BLO - OFF_BHI) + kc * 32 + 16);

            // pass 1: hi*hi -> f32
#pragma unroll
            for (int mt = 0; mt < MT; mt++)
#pragma unroll
                for (int nt = 0; nt < 4; nt++)
                    mma16816_h32(acc[mt][nt], ahi[mt], bh0[nt], bh1[nt]);
            // pass 2: hi*lo' -> f16 corr
#pragma unroll
            for (int mt = 0; mt < MT; mt++)
#pragma unroll
                for (int nt = 0; nt < 4; nt++)
                    mma16816_h16(corr[mt][nt], ahi[mt], bl0[nt], bl1[nt]);
        }

        if (it + 1 < nIt) {
            char* sp = sm + ((it + 1) & 1) * STAGE;
#pragma unroll
            for (int p = 0; p < AP; p++) {
                uint32_t off = (uint32_t)((srow + p * 32) * LDB + sc4 * 8);
                *(uint2*)(sp + off) = pack_f4h(ra[p]);
            }
            CP_WAIT0();
            __syncthreads();
        }
    }

    // merge corrections
#pragma unroll
    for (int mt = 0; mt < MT; mt++)
#pragma unroll
        for (int nt = 0; nt < 4; nt++) {
            __half2 c01 = *(__half2*)&corr[mt][nt][0];
            __half2 c23 = *(__half2*)&corr[mt][nt][1];
            acc[mt][nt][0] += __low2float(c01)  * LO_INV;
            acc[mt][nt][1] += __high2float(c01) * LO_INV;
            acc[mt][nt][2] += __low2float(c23)  * LO_INV;
            acc[mt][nt][3] += __high2float(c23) * LO_INV;
        }

    // ---- epilogue ----
    const int er = m0 + wr * (BM/2) + (lane >> 2);
    const int ec = n0 + wc * 32 + (lane & 3) * 2;
#pragma unroll
    for (int mt = 0; mt < MT; mt++) {
#pragma unroll
        for (int half = 0; half < 2; half++) {
            const int row = er + mt * 16 + half * 8;
            const size_t rb2 = (size_t)row * N;
            const float* rrow = res ? res + rb2 : nullptr;
#pragma unroll
            for (int nt = 0; nt < 4; nt++) {
                const int col = ec + nt * 8;
                float v0 = acc[mt][nt][half * 2 + 0];
                float v1 = acc[mt][nt][half * 2 + 1];
                if (bias) { v0 += bias[col]; v1 += bias[col + 1]; }
                if (gelu) { v0 = gelu_exact(v0); v1 = gelu_exact(v1); }
                if (rrow) { v0 += rrow[col]; v1 += rrow[col + 1]; }
                if (Cf) *(float2*)(Cf + rb2 + col) = make_float2(v0, v1);
                if (Chi) {
                    __nv_bfloat16 h0, l0, h1, l1;
                    split1(v0, h0, l0);
                    split1(v1, h1, l1);
                    *(__nv_bfloat162*)(Chi + rb2 + col) = __nv_bfloat162(h0, h1);
                    *(__nv_bfloat162*)(Clo + rb2 + col) = __nv_bfloat162(l0, l1);
                }
            }
        }
    }
}

// ---------------------------------------------------------------------------
// Batched transpose + fp16 split: src[K,N] fp32 -> dhi/dlo [N,K] fp16
// ---------------------------------------------------------------------------
__global__ void tr_qkv3h(const float* __restrict__ Wq, const float* __restrict__ Wk,
                         const float* __restrict__ Wv,
                         __half* __restrict__ dhi, __half* __restrict__ dlo, int l0)
{
    __shared__ float t[32][33];
    const int z = blockIdx.z;
    const int l = l0 + z / 3;
    const int which = z % 3;
    const float* src = (which == 0 ? Wq : which == 1 ? Wk : Wv)
                     + (size_t)l * DDIM * DDIM;
    const size_t db = (size_t)l * NQKV * DDIM + (size_t)which * DDIM * DDIM;
    const int k0 = blockIdx.y * 32, n0 = blockIdx.x * 32;
    const int tx = threadIdx.x, ty = threadIdx.y;
#pragma unroll
    for (int i = 0; i < 32; i += 8)
        t[ty + i][tx] = src[(size_t)(k0 + ty + i) * DDIM + n0 + tx];
    __syncthreads();
#pragma unroll
    for (int i = 0; i < 32; i += 8) {
        float v = t[tx][ty + i];
        __half hi, lo;
        split1h(v, hi, lo);
        const size_t idx = db + (size_t)(n0 + ty + i) * DDIM + k0 + tx;
        dhi[idx] = hi;
        dlo[idx] = lo;
    }
}

__global__ void transpose_hb(const float* __restrict__ src,
                             __half* __restrict__ dhi, __half* __restrict__ dlo,
                             int K, int N, size_t sstr, size_t dstr)
{
    __shared__ float t[32][33];
    const int l = blockIdx.z;
    src += (size_t)l * sstr;
    dhi += (size_t)l * dstr;
    dlo += (size_t)l * dstr;
    const int k0 = blockIdx.y * 32, n0 = blockIdx.x * 32;
    const int tx = threadIdx.x, ty = threadIdx.y;
#pragma unroll
    for (int i = 0; i < 32; i += 8)
        t[ty + i][tx] = src[(size_t)(k0 + ty + i) * N + n0 + tx];
    __syncthreads();
#pragma unroll
    for (int i = 0; i < 32; i += 8) {
        float v = t[tx][ty + i];
        __half hi, lo;
        split1h(v, hi, lo);
        const size_t idx = (size_t)(n0 + ty + i) * K + k0 + tx;
        dhi[idx] = hi;
        dlo[idx] = lo;
    }
}

// ---------------------------------------------------------------------------
// Fused embedding + bias concat
// ---------------------------------------------------------------------------
__global__ void embed_bias(const int* __restrict__ tokens,
                           const float* __restrict__ emb,
                           const float* __restrict__ pos,
                           float* __restrict__ x,
                           const float* __restrict__ bq, const float* __restrict__ bk,
                           const float* __restrict__ bv, float* __restrict__ bqkv)
{
    if (blockIdx.x < MM) {
        int i = blockIdx.x;
        int s = i & (SSEQ - 1);
        int t = tokens[i];
        const float4* e4 = (const float4*)(emb + (size_t)t * DDIM);
        const float4* p4 = (const float4*)(pos + (size_t)s * DDIM);
        float4*       x4 = (float4*)(x + (size_t)i * DDIM);
        int d = threadIdx.x;
        float4 a = e4[d], b = p4[d];
        x4[d] = make_float4(a.x + b.x, a.y + b.y, a.z + b.z, a.w + b.w);
    } else {
        int e = (blockIdx.x - MM) * 256 + threadIdx.x;
        int l = e / NQKV;
        int i = e - l * NQKV;
        float v;
        if (i < 1024)       v = bq[l * DDIM + i];
        else if (i < 2048)  v = bk[l * DDIM + i - 1024];
        else                v = bv[l * DDIM + i - 2048];
        bqkv[e] = v;
    }
}

// ---------------------------------------------------------------------------
// Tensor-core flash attention (R12-proven, bf16x3), fp32 output
// ---------------------------------------------------------------------------
#define ALDB  144
#define AQHI  0
#define AQLO  18432
#define AKHI  36864
#define AARR  9216
#define ASMEM 73728

__global__ void __launch_bounds__(256, 2)
attn_mma(const __nv_bfloat16* __restrict__ qkvhi,
         const __nv_bfloat16* __restrict__ qkvlo,
         float* __restrict__ o)
{
    extern __shared__ char sm[];
    const uint32_t smb = smem_u32(sm);

    const int tid  = threadIdx.x;
    const int lane = tid & 31;
    const int w    = tid >> 5;
    const int qb   = blockIdx.x;
    const int bh   = blockIdx.y;
    const int b    = bh >> 4;
    const int h    = bh & 15;
    const int rowbase = b * SSEQ;
    const int qc = h * DKV, kc = 1024 + h * DKV, vc = 2048 + h * DKV;

    {
        const int ch  = tid & 7;
        const int wh  = (tid >> 3) & 1;
        const __nv_bfloat16* src = (wh ? qkvlo : qkvhi);
        const uint32_t dstb = smb + (wh ? AQLO : AQHI) + ch * 16;
#pragma unroll
        for (int i = 0; i < 8; i++) {
            const int r = i * 16 + (tid >> 4);
            cp16(dstb + r * ALDB,
                 src + (size_t)(rowbase + qb * 128 + r) * NQKV + qc + ch * 8);
        }
        CP_COMMIT();
    }

    float sO[8][4];
#pragma unroll
    for (int i = 0; i < 8; i++)
#pragma unroll
        for (int q = 0; q < 4; q++) sO[i][q] = 0.0f;
    float mrow[2] = { -INFINITY, -INFINITY };
    float lrow[2] = { 0.0f, 0.0f };

    const int ch  = tid & 7;
    const int arr = (tid >> 3) & 3;
    const __nv_bfloat16* kvsrc =
        (arr == 0) ? qkvhi : (arr == 1) ? qkvlo : (arr == 2) ? qkvhi : qkvlo;
    const int kvcol = (arr < 2) ? kc : vc;
    const uint32_t kvdstb = smb + AKHI + arr * AARR + ch * 16;

    const int ntile = 2 * (qb + 1);
    for (int kt = 0; kt < ntile; kt++) {
        __syncthreads();
        {
#pragma unroll
            for (int i = 0; i < 8; i++) {
                const int r = i * 8 + (tid >> 5);
                cp16(kvdstb + r * ALDB,
                     kvsrc + (size_t)(rowbase + kt * 64 + r) * NQKV + kvcol + ch * 8);
            }
            CP_COMMIT();
        }
        CP_WAIT0();
        __syncthreads();

        float s[8][4];
#pragma unroll
        for (int i = 0; i < 8; i++)
#pragma unroll
            for (int q = 0; q < 4; q++) s[i][q] = 0.0f;

        const uint32_t qHiB = smb + AQHI
            + (uint32_t)((w * 16 + (lane & 15)) * ALDB + (lane >> 4) * 16);
        const uint32_t kHiB0 = smb + AKHI + (uint32_t)(lane * ALDB);

#pragma unroll
        for (int ks = 0; ks < 4; ks++) {
            uint32_t aH[4], aL[4];
            ldmx4(aH, qHiB + ks * 32);
            ldmx4(aL, qHiB + (AQLO - AQHI) + ks * 32);
#pragma unroll
            for (int nb = 0; nb < 2; nb++) {
                const uint32_t kb = kHiB0 + nb * 32 * ALDB + ks * 32;
                uint32_t bh0[4], bh1[4], bl0[4], bl1[4];
                ldmx4(bh0, kb);
                ldmx4(bh1, kb + 16);
                ldmx4(bl0, kb + AARR);
                ldmx4(bl1, kb + AARR + 16);
#pragma unroll
                for (int nt = 0; nt < 4; nt++)
                    mma16816(s[nb * 4 + nt], aH, bh0[nt], bh1[nt]);
#pragma unroll
                for (int nt = 0; nt < 4; nt++)
                    mma16816(s[nb * 4 + nt], aH, bl0[nt], bl1[nt]);
#pragma unroll
                for (int nt = 0; nt < 4; nt++)
                    mma16816(s[nb * 4 + nt], aL, bh0[nt], bh1[nt]);
            }
        }

        const int r0 = qb * 128 + w * 16 + (lane >> 2);
        const int c0 = kt * 64 + (lane & 3) * 2;
#pragma unroll
        for (int nf = 0; nf < 8; nf++) {
            const int col = c0 + nf * 8;
#pragma unroll
            for (int q = 0; q < 4; q++) {
                const int row = r0 + (q >> 1) * 8;
                const int cc  = col + (q & 1);
                float v = s[nf][q] * 0.125f;
                s[nf][q] = (cc > row) ? -INFINITY : v;
            }
        }

        float mx0 = s[0][0], mx1 = s[0][2];
#pragma unroll
        for (int nf = 0; nf < 8; nf++) {
            mx0 = fmaxf(mx0, fmaxf(s[nf][0], s[nf][1]));
            mx1 = fmaxf(mx1, fmaxf(s[nf][2], s[nf][3]));
        }
        mx0 = fmaxf(mx0, __shfl_xor_sync(0xffffffffu, mx0, 1));
        mx0 = fmaxf(mx0, __shfl_xor_sync(0xffffffffu, mx0, 2));
        mx1 = fmaxf(mx1, __shfl_xor_sync(0xffffffffu, mx1, 1));
        mx1 = fmaxf(mx1, __shfl_xor_sync(0xffffffffu, mx1, 2));

        const float mn0 = fmaxf(mrow[0], mx0);
        const float mn1 = fmaxf(mrow[1], mx1);
        const float co0 = __expf(mrow[0] - mn0);
        const float co1 = __expf(mrow[1] - mn1);
        lrow[0] *= co0; lrow[1] *= co1;
#pragma unroll
        for (int nf = 0; nf < 8; nf++) {
            sO[nf][0] *= co0; sO[nf][1] *= co0;
            sO[nf][2] *= co1; sO[nf][3] *= co1;
        }
        float su0 = 0.0f, su1 = 0.0f;
#pragma unroll
        for (int nf = 0; nf < 8; nf++) {
            s[nf][0] = __expf(s[nf][0] - mn0); su0 += s[nf][0];
            s[nf][1] = __expf(s[nf][1] - mn0); su0 += s[nf][1];
            s[nf][2] = __expf(s[nf][2] - mn1); su1 += s[nf][2];
            s[nf][3] = __expf(s[nf][3] - mn1); su1 += s[nf][3];
        }
        su0 += __shfl_xor_sync(0xffffffffu, su0, 1);
        su0 += __shfl_xor_sync(0xffffffffu, su0, 2);
        su1 += __shfl_xor_sync(0xffffffffu, su1, 1);
        su1 += __shfl_xor_sync(0xffffffffu, su1, 2);
        lrow[0] += su0; lrow[1] += su1;
        mrow[0] = mn0; mrow[1] = mn1;

        const uint32_t vHiB0 = smb + AKHI + 2 * AARR
            + (uint32_t)((lane & 15) * ALDB + (lane >> 4) * 16);
#pragma unroll
        for (int ks = 0; ks < 4; ks++) {
            uint32_t pa_h[4], pa_l[4];
            {
                __nv_bfloat16 h0, l0, h1, l1;
                split1(s[2*ks][0], h0, l0); split1(s[2*ks][1], h1, l1);
                pa_h[0] = ((uint32_t)__bfloat16_as_ushort(h1) << 16) | __bfloat16_as_ushort(h0);
                pa_l[0] = ((uint32_t)__bfloat16_as_ushort(l1) << 16) | __bfloat16_as_ushort(l0);
                split1(s[2*ks][2], h0, l0); split1(s[2*ks][3], h1, l1);
                pa_h[1] = ((uint32_t)__bfloat16_as_ushort(h1) << 16) | __bfloat16_as_ushort(h0);
                pa_l[1] = ((uint32_t)__bfloat16_as_ushort(l1) << 16) | __bfloat16_as_ushort(l0);
                split1(s[2*ks+1][0], h0, l0); split1(s[2*ks+1][1], h1, l1);
                pa_h[2] = ((uint32_t)__bfloat16_as_ushort(h1) << 16) | __bfloat16_as_ushort(h0);
                pa_l[2] = ((uint32_t)__bfloat16_as_ushort(l1) << 16) | __bfloat16_as_ushort(l0);
                split1(s[2*ks+1][2], h0, l0); split1(s[2*ks+1][3], h1, l1);
                pa_h[3] = ((uint32_t)__bfloat16_as_ushort(h1) << 16) | __bfloat16_as_ushort(h0);
                pa_l[3] = ((uint32_t)__bfloat16_as_ushort(l1) << 16) | __bfloat16_as_ushort(l0);
            }
#pragma unroll
            for (int nb = 0; nb < 4; nb++) {
                const uint32_t vb = vHiB0 + ks * 16 * ALDB + nb * 32;
                uint32_t vh[4], vl[4];
                ldmx4t(vh, vb);
                ldmx4t(vl, vb + AARR);
                float* d0 = sO[nb * 2];
                float* d1 = sO[nb * 2 + 1];
                mma16816(d0, pa_h, vh[0], vh[1]);
                mma16816(d1, pa_h, vh[2], vh[3]);
                mma16816(d0, pa_h, vl[0], vl[1]);
                mma16816(d1, pa_h, vl[2], vl[3]);
                mma16816(d0, pa_l, vh[0], vh[1]);
                mma16816(d1, pa_l, vh[2], vh[3]);
            }
        }
    }

    const float inv0 = 1.0f / lrow[0];
    const float inv1 = 1.0f / lrow[1];
    const int gr0 = rowbase + qb * 128 + w * 16 + (lane >> 2);
    const int colb = h * DKV + (lane & 3) * 2;
#pragma unroll
    for (int nf = 0; nf < 8; nf++) {
        const int col = colb + nf * 8;
        *(float2*)(o + (size_t)gr0 * DDIM + col) =
            make_float2(sO[nf][0] * inv0, sO[nf][1] * inv0);
        *(float2*)(o + (size_t)(gr0 + 8) * DDIM + col) =
            make_float2(sO[nf][2] * inv1, sO[nf][3] * inv1);
    }
}

// ---------------------------------------------------------------------------
// Host
// ---------------------------------------------------------------------------
#define GSMEM128 (2 * (128 + 256) * LDB)   // 61440
#define GSMEM64  (2 * (64  + 256) * LDB)   // 51200

static inline void run_gemm(const float* A, const __half* Bhi, const __half* Blo,
                            const float* bias, const float* res, float* Cf,
                            __nv_bfloat16* Chi, __nv_bfloat16* Clo,
                            int M, int N, int K, int gelu, int bm64)
{
    if (bm64) {
        dim3 grid(N / 128, M / 64);
        gemm_mma<64,2><<<grid, 256, GSMEM64>>>(A, Bhi, Blo, bias, res, Cf, Chi, Clo,
                                               M, N, K, gelu);
    } else {
        dim3 grid(N / 128, M / 128);
        gemm_mma<128,1><<<grid, 256, GSMEM128>>>(A, Bhi, Blo, bias, res, Cf, Chi, Clo,
                                                 M, N, K, gelu);
    }
}

extern "C" void kernel_launch(void* const* d_in, const int* in_sizes, int n_in,
                              void* d_out, int out_size)
{
    const int*   tokens = (const int*)  d_in[0];
    const float* emb    = (const float*)d_in[1];
    const float* pos    = (const float*)d_in[2];
    const float* Wq     = (const float*)d_in[3];
    const float* bq     = (const float*)d_in[4];
    const float* Wk     = (const float*)d_in[5];
    const float* bk     = (const float*)d_in[6];
    const float* Wv     = (const float*)d_in[7];
    const float* bv     = (const float*)d_in[8];
    const float* Wo     = (const float*)d_in[9];
    const float* W1     = (const float*)d_in[10];
    const float* b1     = (const float*)d_in[11];
    const float* W2     = (const float*)d_in[12];
    const float* b2     = (const float*)d_in[13];
    const float* Wr     = (const float*)d_in[14];
    const float* br     = (const float*)d_in[15];
    float*       out    = (float*)d_out;

    float *x, *o, *h, *t, *bqkv;
    __nv_bfloat16 *qkvhi, *qkvlo;
    __half *Wqkv_hi, *Wqkv_lo, *Wo_hi, *Wo_lo, *W1_hi, *W1_lo;
    __half *W2_hi, *W2_lo, *Wr_hi, *Wr_lo;
    cudaGetSymbolAddress((void**)&x,     g_x);
    cudaGetSymbolAddress((void**)&o,     g_o);
    cudaGetSymbolAddress((void**)&h,     g_h);
    cudaGetSymbolAddress((void**)&t,     g_t);
    cudaGetSymbolAddress((void**)&qkvhi, g_qkvhi);
    cudaGetSymbolAddress((void**)&qkvlo, g_qkvlo);
    cudaGetSymbolAddress((void**)&bqkv,  g_bqkv);
    cudaGetSymbolAddress((void**)&Wqkv_hi, g_Wqkv_hi);
    cudaGetSymbolAddress((void**)&Wqkv_lo, g_Wqkv_lo);
    cudaGetSymbolAddress((void**)&Wo_hi, g_Wo_hi);
    cudaGetSymbolAddress((void**)&Wo_lo, g_Wo_lo);
    cudaGetSymbolAddress((void**)&W1_hi, g_W1_hi);
    cudaGetSymbolAddress((void**)&W1_lo, g_W1_lo);
    cudaGetSymbolAddress((void**)&W2_hi, g_W2_hi);
    cudaGetSymbolAddress((void**)&W2_lo, g_W2_lo);
    cudaGetSymbolAddress((void**)&Wr_hi, g_Wr_hi);
    cudaGetSymbolAddress((void**)&Wr_lo, g_Wr_lo);

    cudaFuncSetAttribute((const void*)gemm_mma<128,1>,
                         cudaFuncAttributeMaxDynamicSharedMemorySize, GSMEM128);
    cudaFuncSetAttribute((const void*)gemm_mma<64,2>,
                         cudaFuncAttributeMaxDynamicSharedMemorySize, GSMEM64);
    cudaFuncSetAttribute(attn_mma,
                         cudaFuncAttributeMaxDynamicSharedMemorySize, ASMEM);

    const size_t DD2 = (size_t)DDIM * DDIM;

    // launch 0: layer-0 QKV weight transpose+split
    tr_qkv3h<<<dim3(32, 32, 3), dim3(32, 8)>>>(Wq, Wk, Wv, Wqkv_hi, Wqkv_lo, 0);
    // launch 1: Wo transpose+split, all layers
    transpose_hb<<<dim3(32, 32, LLAY), dim3(32, 8)>>>(Wo, Wo_hi, Wo_lo,
                                                      DDIM, DDIM, DD2, DD2);
    // launch 2: embed + bias concat
    embed_bias<<<MM + 96, 256>>>(tokens, emb, pos, x, bq, bk, bv, bqkv);
    // launch 3: layer-0 QKV GEMM
    run_gemm(x, Wqkv_hi, Wqkv_lo, bqkv, nullptr,
             nullptr, qkvhi, qkvlo, MM, NQKV, DDIM, 0, 0);
    // launch 4: layer-0 attention
    attn_mma<<<dim3(SSEQ/128, BB*HHH), 256, ASMEM>>>(qkvhi, qkvlo, o);
    // launch 5: layer-0 Wo GEMM (BM=64)
    run_gemm(o, Wo_hi, Wo_lo, nullptr, x, h, nullptr, nullptr, MM, DDIM, DDIM, 0, 1);

    // remaining weight prep
    tr_qkv3h<<<dim3(32, 32, 21), dim3(32, 8)>>>(Wq, Wk, Wv, Wqkv_hi, Wqkv_lo, 1);
    transpose_hb<<<dim3(128, 32, LLAY), dim3(32, 8)>>>(W1, W1_hi, W1_lo,
        DDIM, DHH, (size_t)DDIM*DHH, (size_t)DHH*DDIM);
    transpose_hb<<<dim3(32, 128, LLAY), dim3(32, 8)>>>(W2, W2_hi, W2_lo,
        DHH, DDIM, (size_t)DHH*DDIM, (size_t)DDIM*DHH);
    transpose_hb<<<dim3(8, 32, 1), dim3(32, 8)>>>(Wr, Wr_hi, Wr_lo,
        DDIM, VVOC, 0, 0);

    // layer-0 MLP
    run_gemm(h, W1_hi, W1_lo, b1, nullptr, t, nullptr, nullptr, MM, DHH, DDIM, 1, 0);
    run_gemm(t, W2_hi, W2_lo, b2, h, x, nullptr, nullptr, MM, DDIM, DHH, 0, 1);

    for (int l = 1; l < LLAY; l++) {
        run_gemm(x, Wqkv_hi + (size_t)l*NQKV*DDIM, Wqkv_lo + (size_t)l*NQKV*DDIM,
                 bqkv + (size_t)l*NQKV, nullptr,
                 nullptr, qkvhi, qkvlo, MM, NQKV, DDIM, 0, 0);
        attn_mma<<<dim3(SSEQ/128, BB*HHH), 256, ASMEM>>>(qkvhi, qkvlo, o);
        run_gemm(o, Wo_hi + (size_t)l*DD2, Wo_lo + (size_t)l*DD2,
                 nullptr, x, h, nullptr, nullptr, MM, DDIM, DDIM, 0, 1);
        run_gemm(h, W1_hi + (size_t)l*DHH*DDIM, W1_lo + (size_t)l*DHH*DDIM,
                 b1 + (size_t)l*DHH, nullptr,
                 t, nullptr, nullptr, MM, DHH, DDIM, 1, 0);
        run_gemm(t, W2_hi + (size_t)l*DDIM*DHH, W2_lo + (size_t)l*DDIM*DHH,
                 b2 + (size_t)l*DDIM, h, x, nullptr, nullptr, MM, DDIM, DHH, 0, 1);
    }

    // LM head (BM=64)
    run_gemm(x, Wr_hi, Wr_lo, br, nullptr, out, nullptr, nullptr, MM, VVOC, DDIM, 0, 1);
}

// round 17
// speedup vs baseline: 1.0737x; 1.0737x over previous
#include <cuda_runtime.h>
#include <cuda_bf16.h>
#include <cuda_fp16.h>
#include <math.h>
#include <stdint.h>

// ---------------------------------------------------------------------------
// Problem constants
// ---------------------------------------------------------------------------
#define BB    2
#define SSEQ  1024
#define DDIM  1024
#define HHH   16
#define DKV   64
#define DHH   4096
#define LLAY  8
#define VVOC  256
#define MM    (BB*SSEQ)        // 2048
#define NQKV  3072

// ---------------------------------------------------------------------------
// Scratch (device globals: allocation-free)
// ---------------------------------------------------------------------------
__device__ float g_x   [MM*DDIM];
__device__ float g_o   [MM*DDIM];
__device__ float g_h   [MM*DDIM];
__device__ float g_t   [MM*DHH];
__device__ __nv_bfloat16 g_qkvhi[MM*NQKV], g_qkvlo[MM*NQKV];

__device__ float g_WqkvT[LLAY*NQKV*DDIM];
__device__ float g_WoT  [LLAY*DDIM*DDIM];
__device__ float g_W1T  [LLAY*DHH*DDIM];
__device__ float g_W2T  [LLAY*DDIM*DHH];
__device__ float g_WrT  [VVOC*DDIM];
__device__ float g_bqkv [LLAY*NQKV];

// ---------------------------------------------------------------------------
// Helpers
// ---------------------------------------------------------------------------
__device__ __forceinline__ uint32_t smem_u32(const void* p) {
    uint32_t a;
    asm("{ .reg .u64 t; cvta.to.shared.u64 t, %1; cvt.u32.u64 %0, t; }"
        : "=r"(a) : "l"(p));
    return a;
}

__device__ __forceinline__ void ldmx4(uint32_t* r, uint32_t addr) {
    asm volatile("ldmatrix.sync.aligned.m8n8.x4.shared.b16 {%0,%1,%2,%3}, [%4];"
        : "=r"(r[0]), "=r"(r[1]), "=r"(r[2]), "=r"(r[3]) : "r"(addr));
}

__device__ __forceinline__ void ldmx4t(uint32_t* r, uint32_t addr) {
    asm volatile("ldmatrix.sync.aligned.m8n8.x4.trans.shared.b16 {%0,%1,%2,%3}, [%4];"
        : "=r"(r[0]), "=r"(r[1]), "=r"(r[2]), "=r"(r[3]) : "r"(addr));
}

// bf16 inputs, f32 acc (attention)
__device__ __forceinline__ void mma16816(float* d, const uint32_t* a,
                                         uint32_t b0, uint32_t b1) {
    asm volatile("mma.sync.aligned.m16n8k16.row.col.f32.bf16.bf16.f32 "
        "{%0,%1,%2,%3}, {%4,%5,%6,%7}, {%8,%9}, {%0,%1,%2,%3};"
        : "+f"(d[0]), "+f"(d[1]), "+f"(d[2]), "+f"(d[3])
        : "r"(a[0]), "r"(a[1]), "r"(a[2]), "r"(a[3]), "r"(b0), "r"(b1));
}

// f16 inputs, f32 acc (GEMM main pass)
__device__ __forceinline__ void mma16816_h32(float* d, const uint32_t* a,
                                             uint32_t b0, uint32_t b1) {
    asm volatile("mma.sync.aligned.m16n8k16.row.col.f32.f16.f16.f32 "
        "{%0,%1,%2,%3}, {%4,%5,%6,%7}, {%8,%9}, {%0,%1,%2,%3};"
        : "+f"(d[0]), "+f"(d[1]), "+f"(d[2]), "+f"(d[3])
        : "r"(a[0]), "r"(a[1]), "r"(a[2]), "r"(a[3]), "r"(b0), "r"(b1));
}

// f16 inputs, f16 acc (GEMM correction pass)
__device__ __forceinline__ void mma16816_h16(uint32_t* d, const uint32_t* a,
                                             uint32_t b0, uint32_t b1) {
    asm volatile("mma.sync.aligned.m16n8k16.row.col.f16.f16.f16.f16 "
        "{%0,%1}, {%2,%3,%4,%5}, {%6,%7}, {%0,%1};"
        : "+r"(d[0]), "+r"(d[1])
        : "r"(a[0]), "r"(a[1]), "r"(a[2]), "r"(a[3]), "r"(b0), "r"(b1));
}

__device__ __forceinline__ void cp16(uint32_t dst, const void* src) {
    asm volatile("cp.async.cg.shared.global [%0], [%1], 16;"
        :: "r"(dst), "l"(src) : "memory");
}
#define CP_COMMIT() asm volatile("cp.async.commit_group;" ::: "memory")
#define CP_WAIT0()  asm volatile("cp.async.wait_group 0;" ::: "memory")

__device__ __forceinline__ float gelu_exact(float v) {
    return 0.5f * v * (1.0f + erff(v * 0.70710678118654752f));
}

#define LO_SCALE 4096.0f
#define LO_INV   (1.0f/4096.0f)

// fp16 hi-only pack (A staging)
__device__ __forceinline__ uint2 pack_f4h(float4 v) {
    __half2 p0 = __halves2half2(__float2half_rn(v.x), __float2half_rn(v.y));
    __half2 p1 = __halves2half2(__float2half_rn(v.z), __float2half_rn(v.w));
    uint2 r;
    r.x = *(uint32_t*)&p0;
    r.y = *(uint32_t*)&p1;
    return r;
}

// fp16 split: hi = f16(v), lo = f16((v-hi)*4096)
__device__ __forceinline__ void split_f4h(float4 v, uint2& hi, uint2& lo) {
    __half h0 = __float2half_rn(v.x);
    __half h1 = __float2half_rn(v.y);
    __half h2 = __float2half_rn(v.z);
    __half h3 = __float2half_rn(v.w);
    __half l0 = __float2half_rn((v.x - __half2float(h0)) * LO_SCALE);
    __half l1 = __float2half_rn((v.y - __half2float(h1)) * LO_SCALE);
    __half l2 = __float2half_rn((v.z - __half2float(h2)) * LO_SCALE);
    __half l3 = __float2half_rn((v.w - __half2float(h3)) * LO_SCALE);
    __half2 hp0 = __halves2half2(h0, h1), hp1 = __halves2half2(h2, h3);
    __half2 lp0 = __halves2half2(l0, l1), lp1 = __halves2half2(l2, l3);
    hi.x = *(uint32_t*)&hp0; hi.y = *(uint32_t*)&hp1;
    lo.x = *(uint32_t*)&lp0; lo.y = *(uint32_t*)&lp1;
}

__device__ __forceinline__ void split1(float v, __nv_bfloat16& hi, __nv_bfloat16& lo) {
    hi = __float2bfloat16(v);
    lo = __float2bfloat16(v - __bfloat162float(hi));
}

// ---------------------------------------------------------------------------
// GEMM (R12-proven): C = act(A @ Bt^T + bias) + res; fp32 in, fp16 split
// in-kernel. 2-pass: D = Ahi*Bhi (f32 acc) + Ahi*Blo' (f16 acc, lo scaled 2^12).
// BM in {128, 64}; BN = 128; BK = 32; 8 warps; double-buffered smem.
// ---------------------------------------------------------------------------
#define LDB 80

template<int BM, int MINB>
__global__ void __launch_bounds__(256, MINB)
gemm_mma(const float* __restrict__ A, const float* __restrict__ Bt,
         const float* __restrict__ bias, const float* __restrict__ res,
         float* __restrict__ Cf,
         __nv_bfloat16* __restrict__ Chi, __nv_bfloat16* __restrict__ Clo,
         int M, int N, int K, int gelu)
{
    constexpr int MT      = BM / 32;
    constexpr int AP      = BM / 32;
    constexpr int OFF_BHI = BM * LDB;
    constexpr int OFF_BLO = (BM + 128) * LDB;
    constexpr int STAGE   = (BM + 256) * LDB;

    extern __shared__ char sm[];
    const uint32_t smb = smem_u32(sm);

    const int tid  = threadIdx.x;
    const int lane = tid & 31;
    const int wid  = tid >> 5;
    const int wr   = wid >> 2;
    const int wc   = wid & 3;
    const int m0   = blockIdx.y * BM;
    const int n0   = blockIdx.x * 128;

    const int sc4  = tid & 7;
    const int srow = tid >> 3;
    const float* aP = A  + (size_t)(m0 + srow) * K + sc4 * 4;
    const float* bP = Bt + (size_t)(n0 + srow) * K + sc4 * 4;

    float acc[MT][4][4];
    uint32_t corr[MT][4][2];
#pragma unroll
    for (int i = 0; i < MT; i++)
#pragma unroll
        for (int j = 0; j < 4; j++) {
#pragma unroll
            for (int q = 0; q < 4; q++) acc[i][j][q] = 0.0f;
            corr[i][j][0] = 0u; corr[i][j][1] = 0u;
        }

    float4 ra[AP], rb[4];
#pragma unroll
    for (int p = 0; p < AP; p++)
        ra[p] = __ldg((const float4*)(aP + (size_t)p * 32 * K));
#pragma unroll
    for (int p = 0; p < 4; p++)
        rb[p] = __ldg((const float4*)(bP + (size_t)p * 32 * K));
    {
        char* sp = sm;
#pragma unroll
        for (int p = 0; p < AP; p++) {
            uint32_t off = (uint32_t)((srow + p * 32) * LDB + sc4 * 8);
            *(uint2*)(sp + off) = pack_f4h(ra[p]);
        }
#pragma unroll
        for (int p = 0; p < 4; p++) {
            uint32_t off = (uint32_t)((srow + p * 32) * LDB + sc4 * 8);
            uint2 hi, lo;
            split_f4h(rb[p], hi, lo);
            *(uint2*)(sp + OFF_BHI + off) = hi;
            *(uint2*)(sp + OFF_BLO + off) = lo;
        }
    }
    __syncthreads();

    const int nIt = K >> 5;
    for (int it = 0; it < nIt; ++it) {
        const int cur = it & 1;

        if (it + 1 < nIt) {
#pragma unroll
            for (int p = 0; p < AP; p++)
                ra[p] = __ldg((const float4*)(aP + (it + 1) * 32 + (size_t)p * 32 * K));
#pragma unroll
            for (int p = 0; p < 4; p++)
                rb[p] = __ldg((const float4*)(bP + (it + 1) * 32 + (size_t)p * 32 * K));
        }

        const uint32_t stage = smb + cur * STAGE;
        const uint32_t aHiB = stage
            + (uint32_t)((wr * (BM/2) + (lane & 15)) * LDB + (lane >> 4) * 16);
        const uint32_t bHiB = stage + OFF_BHI + (uint32_t)((wc * 32 + lane) * LDB);

#pragma unroll
        for (int kc = 0; kc < 2; kc++) {
            uint32_t ahi[MT][4];
            uint32_t bh0[4], bh1[4], bl0[4], bl1[4];
#pragma unroll
            for (int mt = 0; mt < MT; mt++)
                ldmx4(ahi[mt], aHiB + mt * 16 * LDB + kc * 32);
            ldmx4(bh0, bHiB + kc * 32);
            ldmx4(bh1, bHiB + kc * 32 + 16);
            ldmx4(bl0, bHiB + (OFF_BLO - OFF_BHI) + kc * 32);
            ldmx4(bl1, bHiB + (OFF_BLO - OFF_BHI) + kc * 32 + 16);

            // pass 1: hi*hi -> f32
#pragma unroll
            for (int mt = 0; mt < MT; mt++)
#pragma unroll
                for (int nt = 0; nt < 4; nt++)
                    mma16816_h32(acc[mt][nt], ahi[mt], bh0[nt], bh1[nt]);
            // pass 2: hi*lo' -> f16 corr
#pragma unroll
            for (int mt = 0; mt < MT; mt++)
#pragma unroll
                for (int nt = 0; nt < 4; nt++)
                    mma16816_h16(corr[mt][nt], ahi[mt], bl0[nt], bl1[nt]);
        }

        if (it + 1 < nIt) {
            char* sp = sm + ((it + 1) & 1) * STAGE;
#pragma unroll
            for (int p = 0; p < AP; p++) {
                uint32_t off = (uint32_t)((srow + p * 32) * LDB + sc4 * 8);
                *(uint2*)(sp + off) = pack_f4h(ra[p]);
            }
#pragma unroll
            for (int p = 0; p < 4; p++) {
                uint32_t off = (uint32_t)((srow + p * 32) * LDB + sc4 * 8);
                uint2 hi, lo;
                split_f4h(rb[p], hi, lo);
                *(uint2*)(sp + OFF_BHI + off) = hi;
                *(uint2*)(sp + OFF_BLO + off) = lo;
            }
        }
        __syncthreads();
    }

    // merge corrections
#pragma unroll
    for (int mt = 0; mt < MT; mt++)
#pragma unroll
        for (int nt = 0; nt < 4; nt++) {
            __half2 c01 = *(__half2*)&corr[mt][nt][0];
            __half2 c23 = *(__half2*)&corr[mt][nt][1];
            acc[mt][nt][0] += __low2float(c01)  * LO_INV;
            acc[mt][nt][1] += __high2float(c01) * LO_INV;
            acc[mt][nt][2] += __low2float(c23)  * LO_INV;
            acc[mt][nt][3] += __high2float(c23) * LO_INV;
        }

    // ---- epilogue ----
    const int er = m0 + wr * (BM/2) + (lane >> 2);
    const int ec = n0 + wc * 32 + (lane & 3) * 2;
#pragma unroll
    for (int mt = 0; mt < MT; mt++) {
#pragma unroll
        for (int half = 0; half < 2; half++) {
            const int row = er + mt * 16 + half * 8;
            const size_t rb2 = (size_t)row * N;
            const float* rrow = res ? res + rb2 : nullptr;
#pragma unroll
            for (int nt = 0; nt < 4; nt++) {
                const int col = ec + nt * 8;
                float v0 = acc[mt][nt][half * 2 + 0];
                float v1 = acc[mt][nt][half * 2 + 1];
                if (bias) { v0 += bias[col]; v1 += bias[col + 1]; }
                if (gelu) { v0 = gelu_exact(v0); v1 = gelu_exact(v1); }
                if (rrow) { v0 += rrow[col]; v1 += rrow[col + 1]; }
                if (Cf) *(float2*)(Cf + rb2 + col) = make_float2(v0, v1);
                if (Chi) {
                    __nv_bfloat16 h0, l0, h1, l1;
                    split1(v0, h0, l0);
                    split1(v1, h1, l1);
                    *(__nv_bfloat162*)(Chi + rb2 + col) = __nv_bfloat162(h0, h1);
                    *(__nv_bfloat162*)(Clo + rb2 + col) = __nv_bfloat162(l0, l1);
                }
            }
        }
    }
}

// ---------------------------------------------------------------------------
// Batched transposes
// ---------------------------------------------------------------------------
__global__ void tr_qkv3(const float* __restrict__ Wq, const float* __restrict__ Wk,
                        const float* __restrict__ Wv, float* __restrict__ dst,
                        int l0)
{
    __shared__ float t[32][33];
    const int z = blockIdx.z;
    const int l = l0 + z / 3;
    const int which = z % 3;
    const float* src = (which == 0 ? Wq : which == 1 ? Wk : Wv)
                     + (size_t)l * DDIM * DDIM;
    float* d = dst + (size_t)l * NQKV * DDIM + (size_t)which * DDIM * DDIM;
    const int k0 = blockIdx.y * 32, n0 = blockIdx.x * 32;
    const int tx = threadIdx.x, ty = threadIdx.y;
#pragma unroll
    for (int i = 0; i < 32; i += 8)
        t[ty + i][tx] = src[(size_t)(k0 + ty + i) * DDIM + n0 + tx];
    __syncthreads();
#pragma unroll
    for (int i = 0; i < 32; i += 8)
        d[(size_t)(n0 + ty + i) * DDIM + k0 + tx] = t[tx][ty + i];
}

__global__ void transpose_b(const float* __restrict__ src, float* __restrict__ dst,
                            int K, int N, size_t sstr, size_t dstr)
{
    __shared__ float t[32][33];
    const int l = blockIdx.z;
    src += (size_t)l * sstr;
    dst += (size_t)l * dstr;
    const int k0 = blockIdx.y * 32, n0 = blockIdx.x * 32;
    const int tx = threadIdx.x, ty = threadIdx.y;
#pragma unroll
    for (int i = 0; i < 32; i += 8)
        t[ty + i][tx] = src[(size_t)(k0 + ty + i) * N + n0 + tx];
    __syncthreads();
#pragma unroll
    for (int i = 0; i < 32; i += 8)
        dst[(size_t)(n0 + ty + i) * K + k0 + tx] = t[tx][ty + i];
}

// ---------------------------------------------------------------------------
// Fused embedding + bias concat
// ---------------------------------------------------------------------------
__global__ void embed_bias(const int* __restrict__ tokens,
                           const float* __restrict__ emb,
                           const float* __restrict__ pos,
                           float* __restrict__ x,
                           const float* __restrict__ bq, const float* __restrict__ bk,
                           const float* __restrict__ bv, float* __restrict__ bqkv)
{
    if (blockIdx.x < MM) {
        int i = blockIdx.x;
        int s = i & (SSEQ - 1);
        int t = tokens[i];
        const float4* e4 = (const float4*)(emb + (size_t)t * DDIM);
        const float4* p4 = (const float4*)(pos + (size_t)s * DDIM);
        float4*       x4 = (float4*)(x + (size_t)i * DDIM);
        int d = threadIdx.x;
        float4 a = e4[d], b = p4[d];
        x4[d] = make_float4(a.x + b.x, a.y + b.y, a.z + b.z, a.w + b.w);
    } else {
        int e = (blockIdx.x - MM) * 256 + threadIdx.x;
        int l = e / NQKV;
        int i = e - l * NQKV;
        float v;
        if (i < 1024)       v = bq[l * DDIM + i];
        else if (i < 2048)  v = bk[l * DDIM + i - 1024];
        else                v = bv[l * DDIM + i - 2048];
        bqkv[e] = v;
    }
}

// ---------------------------------------------------------------------------
// Tensor-core flash attention (R12-proven, bf16x3), fp32 output
// ---------------------------------------------------------------------------
#define ALDB  144
#define AQHI  0
#define AQLO  18432
#define AKHI  36864
#define AARR  9216
#define ASMEM 73728

__global__ void __launch_bounds__(256, 2)
attn_mma(const __nv_bfloat16* __restrict__ qkvhi,
         const __nv_bfloat16* __restrict__ qkvlo,
         float* __restrict__ o)
{
    extern __shared__ char sm[];
    const uint32_t smb = smem_u32(sm);

    const int tid  = threadIdx.x;
    const int lane = tid & 31;
    const int w    = tid >> 5;
    const int qb   = blockIdx.x;
    const int bh   = blockIdx.y;
    const int b    = bh >> 4;
    const int h    = bh & 15;
    const int rowbase = b * SSEQ;
    const int qc = h * DKV, kc = 1024 + h * DKV, vc = 2048 + h * DKV;

    {
        const int ch  = tid & 7;
        const int wh  = (tid >> 3) & 1;
        const __nv_bfloat16* src = (wh ? qkvlo : qkvhi);
        const uint32_t dstb = smb + (wh ? AQLO : AQHI) + ch * 16;
#pragma unroll
        for (int i = 0; i < 8; i++) {
            const int r = i * 16 + (tid >> 4);
            cp16(dstb + r * ALDB,
                 src + (size_t)(rowbase + qb * 128 + r) * NQKV + qc + ch * 8);
        }
        CP_COMMIT();
    }

    float sO[8][4];
#pragma unroll
    for (int i = 0; i < 8; i++)
#pragma unroll
        for (int q = 0; q < 4; q++) sO[i][q] = 0.0f;
    float mrow[2] = { -INFINITY, -INFINITY };
    float lrow[2] = { 0.0f, 0.0f };

    const int ch  = tid & 7;
    const int arr = (tid >> 3) & 3;
    const __nv_bfloat16* kvsrc =
        (arr == 0) ? qkvhi : (arr == 1) ? qkvlo : (arr == 2) ? qkvhi : qkvlo;
    const int kvcol = (arr < 2) ? kc : vc;
    const uint32_t kvdstb = smb + AKHI + arr * AARR + ch * 16;

    const int ntile = 2 * (qb + 1);
    for (int kt = 0; kt < ntile; kt++) {
        __syncthreads();
        {
#pragma unroll
            for (int i = 0; i < 8; i++) {
                const int r = i * 8 + (tid >> 5);
                cp16(kvdstb + r * ALDB,
                     kvsrc + (size_t)(rowbase + kt * 64 + r) * NQKV + kvcol + ch * 8);
            }
            CP_COMMIT();
        }
        CP_WAIT0();
        __syncthreads();

        float s[8][4];
#pragma unroll
        for (int i = 0; i < 8; i++)
#pragma unroll
            for (int q = 0; q < 4; q++) s[i][q] = 0.0f;

        const uint32_t qHiB = smb + AQHI
            + (uint32_t)((w * 16 + (lane & 15)) * ALDB + (lane >> 4) * 16);
        const uint32_t kHiB0 = smb + AKHI + (uint32_t)(lane * ALDB);

#pragma unroll
        for (int ks = 0; ks < 4; ks++) {
            uint32_t aH[4], aL[4];
            ldmx4(aH, qHiB + ks * 32);
            ldmx4(aL, qHiB + (AQLO - AQHI) + ks * 32);
#pragma unroll
            for (int nb = 0; nb < 2; nb++) {
                const uint32_t kb = kHiB0 + nb * 32 * ALDB + ks * 32;
                uint32_t bh0[4], bh1[4], bl0[4], bl1[4];
                ldmx4(bh0, kb);
                ldmx4(bh1, kb + 16);
                ldmx4(bl0, kb + AARR);
                ldmx4(bl1, kb + AARR + 16);
#pragma unroll
                for (int nt = 0; nt < 4; nt++)
                    mma16816(s[nb * 4 + nt], aH, bh0[nt], bh1[nt]);
#pragma unroll
                for (int nt = 0; nt < 4; nt++)
                    mma16816(s[nb * 4 + nt], aH, bl0[nt], bl1[nt]);
#pragma unroll
                for (int nt = 0; nt < 4; nt++)
                    mma16816(s[nb * 4 + nt], aL, bh0[nt], bh1[nt]);
            }
        }

        const int r0 = qb * 128 + w * 16 + (lane >> 2);
        const int c0 = kt * 64 + (lane & 3) * 2;
#pragma unroll
        for (int nf = 0; nf < 8; nf++) {
            const int col = c0 + nf * 8;
#pragma unroll
            for (int q = 0; q < 4; q++) {
                const int row = r0 + (q >> 1) * 8;
                const int cc  = col + (q & 1);
                float v = s[nf][q] * 0.125f;
                s[nf][q] = (cc > row) ? -INFINITY : v;
            }
        }

        float mx0 = s[0][0], mx1 = s[0][2];
#pragma unroll
        for (int nf = 0; nf < 8; nf++) {
            mx0 = fmaxf(mx0, fmaxf(s[nf][0], s[nf][1]));
            mx1 = fmaxf(mx1, fmaxf(s[nf][2], s[nf][3]));
        }
        mx0 = fmaxf(mx0, __shfl_xor_sync(0xffffffffu, mx0, 1));
        mx0 = fmaxf(mx0, __shfl_xor_sync(0xffffffffu, mx0, 2));
        mx1 = fmaxf(mx1, __shfl_xor_sync(0xffffffffu, mx1, 1));
        mx1 = fmaxf(mx1, __shfl_xor_sync(0xffffffffu, mx1, 2));

        const float mn0 = fmaxf(mrow[0], mx0);
        const float mn1 = fmaxf(mrow[1], mx1);
        const float co0 = __expf(mrow[0] - mn0);
        const float co1 = __expf(mrow[1] - mn1);
        lrow[0] *= co0; lrow[1] *= co1;
#pragma unroll
        for (int nf = 0; nf < 8; nf++) {
            sO[nf][0] *= co0; sO[nf][1] *= co0;
            sO[nf][2] *= co1; sO[nf][3] *= co1;
        }
        float su0 = 0.0f, su1 = 0.0f;
#pragma unroll
        for (int nf = 0; nf < 8; nf++) {
            s[nf][0] = __expf(s[nf][0] - mn0); su0 += s[nf][0];
            s[nf][1] = __expf(s[nf][1] - mn0); su0 += s[nf][1];
            s[nf][2] = __expf(s[nf][2] - mn1); su1 += s[nf][2];
            s[nf][3] = __expf(s[nf][3] - mn1); su1 += s[nf][3];
        }
        su0 += __shfl_xor_sync(0xffffffffu, su0, 1);
        su0 += __shfl_xor_sync(0xffffffffu, su0, 2);
        su1 += __shfl_xor_sync(0xffffffffu, su1, 1);
        su1 += __shfl_xor_sync(0xffffffffu, su1, 2);
        lrow[0] += su0; lrow[1] += su1;
        mrow[0] = mn0; mrow[1] = mn1;

        const uint32_t vHiB0 = smb + AKHI + 2 * AARR
            + (uint32_t)((lane & 15) * ALDB + (lane >> 4) * 16);
#pragma unroll
        for (int ks = 0; ks < 4; ks++) {
            uint32_t pa_h[4], pa_l[4];
            {
                __nv_bfloat16 h0, l0, h1, l1;
                split1(s[2*ks][0], h0, l0); split1(s[2*ks][1], h1, l1);
                pa_h[0] = ((uint32_t)__bfloat16_as_ushort(h1) << 16) | __bfloat16_as_ushort(h0);
                pa_l[0] = ((uint32_t)__bfloat16_as_ushort(l1) << 16) | __bfloat16_as_ushort(l0);
                split1(s[2*ks][2], h0, l0); split1(s[2*ks][3], h1, l1);
                pa_h[1] = ((uint32_t)__bfloat16_as_ushort(h1) << 16) | __bfloat16_as_ushort(h0);
                pa_l[1] = ((uint32_t)__bfloat16_as_ushort(l1) << 16) | __bfloat16_as_ushort(l0);
                split1(s[2*ks+1][0], h0, l0); split1(s[2*ks+1][1], h1, l1);
                pa_h[2] = ((uint32_t)__bfloat16_as_ushort(h1) << 16) | __bfloat16_as_ushort(h0);
                pa_l[2] = ((uint32_t)__bfloat16_as_ushort(l1) << 16) | __bfloat16_as_ushort(l0);
                split1(s[2*ks+1][2], h0, l0); split1(s[2*ks+1][3], h1, l1);
                pa_h[3] = ((uint32_t)__bfloat16_as_ushort(h1) << 16) | __bfloat16_as_ushort(h0);
                pa_l[3] = ((uint32_t)__bfloat16_as_ushort(l1) << 16) | __bfloat16_as_ushort(l0);
            }
#pragma unroll
            for (int nb = 0; nb < 4; nb++) {
                const uint32_t vb = vHiB0 + ks * 16 * ALDB + nb * 32;
                uint32_t vh[4], vl[4];
                ldmx4t(vh, vb);
                ldmx4t(vl, vb + AARR);
                float* d0 = sO[nb * 2];
                float* d1 = sO[nb * 2 + 1];
                mma16816(d0, pa_h, vh[0], vh[1]);
                mma16816(d1, pa_h, vh[2], vh[3]);
                mma16816(d0, pa_h, vl[0], vl[1]);
                mma16816(d1, pa_h, vl[2], vl[3]);
                mma16816(d0, pa_l, vh[0], vh[1]);
                mma16816(d1, pa_l, vh[2], vh[3]);
            }
        }
    }

    const float inv0 = 1.0f / lrow[0];
    const float inv1 = 1.0f / lrow[1];
    const int gr0 = rowbase + qb * 128 + w * 16 + (lane >> 2);
    const int colb = h * DKV + (lane & 3) * 2;
#pragma unroll
    for (int nf = 0; nf < 8; nf++) {
        const int col = colb + nf * 8;
        *(float2*)(o + (size_t)gr0 * DDIM + col) =
            make_float2(sO[nf][0] * inv0, sO[nf][1] * inv0);
        *(float2*)(o + (size_t)(gr0 + 8) * DDIM + col) =
            make_float2(sO[nf][2] * inv1, sO[nf][3] * inv1);
    }
}

// ---------------------------------------------------------------------------
// Host
// ---------------------------------------------------------------------------
#define GSMEM128 (2 * (128 + 256) * LDB)   // 61440
#define GSMEM64  (2 * (64  + 256) * LDB)   // 51200

static inline void run_gemm(const float* A, const float* Bt, const float* bias,
                            const float* res, float* Cf,
                            __nv_bfloat16* Chi, __nv_bfloat16* Clo,
                            int M, int N, int K, int gelu, int bm64)
{
    if (bm64) {
        dim3 grid(N / 128, M / 64);
        gemm_mma<64,2><<<grid, 256, GSMEM64>>>(A, Bt, bias, res, Cf, Chi, Clo,
                                               M, N, K, gelu);
    } else {
        dim3 grid(N / 128, M / 128);
        gemm_mma<128,1><<<grid, 256, GSMEM128>>>(A, Bt, bias, res, Cf, Chi, Clo,
                                                 M, N, K, gelu);
    }
}

extern "C" void kernel_launch(void* const* d_in, const int* in_sizes, int n_in,
                              void* d_out, int out_size)
{
    const int*   tokens = (const int*)  d_in[0];
    const float* emb    = (const float*)d_in[1];
    const float* pos    = (const float*)d_in[2];
    const float* Wq     = (const float*)d_in[3];
    const float* bq     = (const float*)d_in[4];
    const float* Wk     = (const float*)d_in[5];
    const float* bk     = (const float*)d_in[6];
    const float* Wv     = (const float*)d_in[7];
    const float* bv     = (const float*)d_in[8];
    const float* Wo     = (const float*)d_in[9];
    const float* W1     = (const float*)d_in[10];
    const float* b1     = (const float*)d_in[11];
    const float* W2     = (const float*)d_in[12];
    const float* b2     = (const float*)d_in[13];
    const float* Wr     = (const float*)d_in[14];
    const float* br     = (const float*)d_in[15];
    float*       out    = (float*)d_out;

    float *x, *o, *h, *t, *bqkv;
    __nv_bfloat16 *qkvhi, *qkvlo;
    float *WqkvT, *WoT, *W1T, *W2T, *WrT;
    cudaGetSymbolAddress((void**)&x,     g_x);
    cudaGetSymbolAddress((void**)&o,     g_o);
    cudaGetSymbolAddress((void**)&h,     g_h);
    cudaGetSymbolAddress((void**)&t,     g_t);
    cudaGetSymbolAddress((void**)&qkvhi, g_qkvhi);
    cudaGetSymbolAddress((void**)&qkvlo, g_qkvlo);
    cudaGetSymbolAddress((void**)&WqkvT, g_WqkvT);
    cudaGetSymbolAddress((void**)&WoT,   g_WoT);
    cudaGetSymbolAddress((void**)&W1T,   g_W1T);
    cudaGetSymbolAddress((void**)&W2T,   g_W2T);
    cudaGetSymbolAddress((void**)&WrT,   g_WrT);
    cudaGetSymbolAddress((void**)&bqkv,  g_bqkv);

    cudaFuncSetAttribute((const void*)gemm_mma<128,1>,
                         cudaFuncAttributeMaxDynamicSharedMemorySize, GSMEM128);
    cudaFuncSetAttribute((const void*)gemm_mma<64,2>,
                         cudaFuncAttributeMaxDynamicSharedMemorySize, GSMEM64);
    cudaFuncSetAttribute(attn_mma,
                         cudaFuncAttributeMaxDynamicSharedMemorySize, ASMEM);

    const size_t DD2 = (size_t)DDIM * DDIM;

    // launch 0: layer-0 QKV weight transpose
    tr_qkv3<<<dim3(32, 32, 3), dim3(32, 8)>>>(Wq, Wk, Wv, WqkvT, 0);
    // launch 1: Wo transpose, all layers
    transpose_b<<<dim3(32, 32, LLAY), dim3(32, 8)>>>(Wo, WoT, DDIM, DDIM, DD2, DD2);
    // launch 2: embed + bias concat
    embed_bias<<<MM + 96, 256>>>(tokens, emb, pos, x, bq, bk, bv, bqkv);
    // launch 3: layer-0 QKV GEMM (BM=64: 768 CTAs, 2/SM -> smaller tail)
    run_gemm(x, WqkvT, bqkv, nullptr, nullptr, qkvhi, qkvlo, MM, NQKV, DDIM, 0, 1);
    // launch 4: layer-0 attention
    attn_mma<<<dim3(SSEQ/128, BB*HHH), 256, ASMEM>>>(qkvhi, qkvlo, o);
    // launch 5: layer-0 Wo GEMM (BM=64)
    run_gemm(o, WoT, nullptr, x, h, nullptr, nullptr, MM, DDIM, DDIM, 0, 1);

    // remaining weight prep
    tr_qkv3<<<dim3(32, 32, 21), dim3(32, 8)>>>(Wq, Wk, Wv, WqkvT, 1);
    transpose_b<<<dim3(128, 32, LLAY), dim3(32, 8)>>>(W1, W1T, DDIM, DHH,
                                                      (size_t)DDIM*DHH, (size_t)DHH*DDIM);
    transpose_b<<<dim3(32, 128, LLAY), dim3(32, 8)>>>(W2, W2T, DHH, DDIM,
                                                      (size_t)DHH*DDIM, (size_t)DDIM*DHH);
    transpose_b<<<dim3(8, 32, 1), dim3(32, 8)>>>(Wr, WrT, DDIM, VVOC, 0, 0);

    // layer-0 MLP (W1 on BM=64 as well)
    run_gemm(h, W1T, b1, nullptr, t, nullptr, nullptr, MM, DHH, DDIM, 1, 1);
    run_gemm(t, W2T, b2, h, x, nullptr, nullptr, MM, DDIM, DHH, 0, 1);

    for (int l = 1; l < LLAY; l++) {
        const float* woT = WoT + (size_t)l*DD2;
        const float* w1T = W1T + (size_t)l*DHH*DDIM;
        const float* w2T = W2T + (size_t)l*DDIM*DHH;

        run_gemm(x, WqkvT + (size_t)l*NQKV*DDIM, bqkv + (size_t)l*NQKV, nullptr,
                 nullptr, qkvhi, qkvlo, MM, NQKV, DDIM, 0, 1);
        attn_mma<<<dim3(SSEQ/128, BB*HHH), 256, ASMEM>>>(qkvhi, qkvlo, o);
        run_gemm(o, woT, nullptr, x, h, nullptr, nullptr, MM, DDIM, DDIM, 0, 1);
        run_gemm(h, w1T, b1 + (size_t)l*DHH, nullptr, t, nullptr, nullptr,
                 MM, DHH, DDIM, 1, 1);
        run_gemm(t, w2T, b2 + (size_t)l*DDIM, h, x, nullptr, nullptr,
                 MM, DDIM, DHH, 0, 1);
    }

    // LM head (BM=64)
    run_gemm(x, WrT, br, nullptr, out, nullptr, nullptr, MM, VVOC, DDIM, 0, 1);
}